// round 6
// baseline (speedup 1.0000x reference)
#include <cuda_runtime.h>
#include <cstdint>

#define N_NODES 100000
#define FEAT    64
#define NF      (N_NODES * FEAT)
#define E_MAX   1700000
#define SCAN_T  1024
#define SCAN_B  ((N_NODES + SCAN_T - 1) / SCAN_T)   // 98

// Scratch: device globals (no allocations allowed).
__device__ __align__(16) float g_u[NF];
__device__ __align__(16) float g_u2[NF];
__device__ int   g_cnt[N_NODES];
__device__ int   g_off[N_NODES + 1];
__device__ int   g_cur[N_NODES];
__device__ int   g_adj[E_MAX];
__device__ int   g_blk[SCAN_B];
__device__ float g_dinv[N_NODES];    // (deg)^{-1/2}, deg includes self-loop
__device__ float g_dinv2[N_NODES];   // (deg)^{-1}
__device__ int   g_is64;             // 1 if edge_index is int64, 0 if int32

// ---------------------------------------------------------------------------
// Deterministic dtype sniff: int64 node ids < 1e5 have zero high words.
__global__ void k_detect(const int* __restrict__ ei32) {
    __shared__ int any;
    if (threadIdx.x == 0) any = 0;
    __syncthreads();
    for (int i = threadIdx.x; i < 1024; i += blockDim.x)
        if (ei32[2 * i + 1] != 0) any = 1;     // benign race, same result
    __syncthreads();
    if (threadIdx.x == 0) g_is64 = (any == 0) ? 1 : 0;
}

__device__ __forceinline__ int edge_idx(const void* ei, int E, int half, int e) {
    if (g_is64) {
        long long v = ((const long long*)ei)[(size_t)half * E + e];
        return (int)v;
    }
    return ((const int*)ei)[(size_t)half * E + e];
}

// ---------------------------------------------------------------------------
__global__ void k_zero() {
    int i = blockIdx.x * blockDim.x + threadIdx.x;
    if (i < N_NODES) g_cnt[i] = 0;
}

__global__ void k_hist(const void* __restrict__ ei, int E) {
    int e = blockIdx.x * blockDim.x + threadIdx.x;
    if (e >= E) return;
    unsigned t = (unsigned)edge_idx(ei, E, 1, e);   // target i
    if (t < N_NODES) atomicAdd(&g_cnt[t], 1);
}

// --- grid-wide exclusive scan of g_cnt, 3 phases --------------------------
__global__ void k_scan1() {
    __shared__ int bs[SCAN_T];
    int i = blockIdx.x * SCAN_T + threadIdx.x;
    int v = (i < N_NODES) ? g_cnt[i] : 0;
    bs[threadIdx.x] = v;
    __syncthreads();
    for (int off = SCAN_T / 2; off > 0; off >>= 1) {
        if (threadIdx.x < off) bs[threadIdx.x] += bs[threadIdx.x + off];
        __syncthreads();
    }
    if (threadIdx.x == 0) g_blk[blockIdx.x] = bs[0];
}

__global__ void k_scan2() {
    __shared__ int bs[128];
    int t = threadIdx.x;
    int v = (t < SCAN_B) ? g_blk[t] : 0;
    bs[t] = v;
    __syncthreads();
    for (int off = 1; off < 128; off <<= 1) {       // Hillis-Steele inclusive
        int p = (t >= off) ? bs[t - off] : 0;
        __syncthreads();
        bs[t] += p;
        __syncthreads();
    }
    if (t < SCAN_B) g_blk[t] = bs[t] - v;           // exclusive
    if (t == 0) g_off[N_NODES] = bs[127];           // total
}

__global__ void k_scan3() {
    __shared__ int bs[SCAN_T];
    int t = threadIdx.x;
    int i = blockIdx.x * SCAN_T + t;
    int c = (i < N_NODES) ? g_cnt[i] : 0;
    bs[t] = c;
    __syncthreads();
    for (int off = 1; off < SCAN_T; off <<= 1) {    // Hillis-Steele inclusive
        int p = (t >= off) ? bs[t - off] : 0;
        __syncthreads();
        bs[t] += p;
        __syncthreads();
    }
    if (i < N_NODES) {
        int excl = g_blk[blockIdx.x] + bs[t] - c;
        g_off[i] = excl;
        g_cur[i] = excl;
        float deg = (float)c + 1.0f;        // self-loop
        g_dinv[i]  = rsqrtf(deg);
        g_dinv2[i] = 1.0f / deg;
    }
}

__global__ void k_scatter(const void* __restrict__ ei, int E) {
    int e = blockIdx.x * blockDim.x + threadIdx.x;
    if (e >= E) return;
    unsigned tgt = (unsigned)edge_idx(ei, E, 1, e);
    unsigned src = (unsigned)edge_idx(ei, E, 0, e);
    if (tgt >= N_NODES || src >= N_NODES) return;
    int pos = atomicAdd(&g_cur[tgt], 1);
    if (pos < E_MAX) g_adj[pos] = (int)src;
}

// ---------------------------------------------------------------------------
// u0[i,:] = dinv[i] * (x[i,:] @ W^T)   -- x:[N,128], W:[64,128]
__global__ void k_gemm(const float* __restrict__ x, const float* __restrict__ W) {
    __shared__ float Ws[128 * 64];   // Ws[k*64 + c] = W[c*128 + k]
    __shared__ float xs[4][128];

    int tid = threadIdx.x;
    // Load W as float4: 2048 float4 total, 8 per thread.
    for (int i = tid; i < 2048; i += 256) {
        float4 w4 = __ldg(&reinterpret_cast<const float4*>(W)[i]);
        int c = i >> 5;            // 32 float4 per row of 128
        int k = (i & 31) << 2;
        Ws[(k + 0) * 64 + c] = w4.x;
        Ws[(k + 1) * 64 + c] = w4.y;
        Ws[(k + 2) * 64 + c] = w4.z;
        Ws[(k + 3) * 64 + c] = w4.w;
    }
    __syncthreads();

    int c = tid & 63;
    int r = tid >> 6;

    for (int rb = blockIdx.x * 4; rb < N_NODES; rb += gridDim.x * 4) {
        // 4 rows x 128 floats = 128 float4; thread i loads one (i<128).
        if (tid < 128) {
            int rr = tid >> 5;           // row 0..3
            int k4 = (tid & 31);         // float4 index within row
            int rowi = rb + rr;
            float4 v = (rowi < N_NODES)
                ? __ldg(&reinterpret_cast<const float4*>(x)[(size_t)rowi * 32 + k4])
                : make_float4(0.f, 0.f, 0.f, 0.f);
            int k = k4 << 2;
            xs[rr][k + 0] = v.x;
            xs[rr][k + 1] = v.y;
            xs[rr][k + 2] = v.z;
            xs[rr][k + 3] = v.w;
        }
        __syncthreads();

        int rowi = rb + r;
        if (rowi < N_NODES) {
            float s = 0.0f;
            #pragma unroll
            for (int k = 0; k < 128; k++)
                s = fmaf(xs[r][k], Ws[k * 64 + c], s);
            g_u[(size_t)rowi * 64 + c] = g_dinv[rowi] * s;
        }
        __syncthreads();
    }
}

// ---------------------------------------------------------------------------
// Gather hop: halfwarp (16 threads) per node, one float4 column-group each.
// Adjacency indices are batch-loaded 16 at a time (one parallel LDG) and
// broadcast via shfl so the u-gathers form a deep independent-load window.
// PASS 0: g_u  -> g_u2, scale dinv2
// PASS 1: g_u2 -> g_u,  scale dinv2
// PASS 2: g_u  -> out,  scale dinv, + bias
template <int PASS>
__global__ void k_hop(float* __restrict__ outp, const float* __restrict__ b) {
    const float4* uin  = reinterpret_cast<const float4*>(PASS == 1 ? g_u2 : g_u);
    float4* uout = (PASS == 0) ? reinterpret_cast<float4*>(g_u2)
                 : (PASS == 1) ? reinterpret_cast<float4*>(g_u)
                               : reinterpret_cast<float4*>(outp);

    int tid  = threadIdx.x;
    int node = blockIdx.x * 16 + (tid >> 4);
    if (node >= N_NODES) return;
    int lane = tid & 15;
    unsigned hm = 0xFFFFu << (threadIdx.x & 16);   // this halfwarp's mask

    int d   = g_off[node];
    int end = g_off[node + 1];

    float4 s = uin[(size_t)node * 16 + lane];      // self-loop term

    for (int base = d; base < end; base += 16) {
        int n = end - base; if (n > 16) n = 16;
        int idx = (lane < n) ? __ldg(&g_adj[base + lane]) : 0;
        #pragma unroll 4
        for (int k = 0; k < n; k++) {
            int j = __shfl_sync(hm, idx, k, 16);
            float4 a = __ldg(&uin[(size_t)j * 16 + lane]);
            s.x += a.x; s.y += a.y; s.z += a.z; s.w += a.w;
        }
    }

    float4 o;
    if (PASS == 2) {
        float sc = g_dinv[node];
        int cb = lane << 2;
        o.x = sc * s.x + __ldg(&b[cb + 0]);
        o.y = sc * s.y + __ldg(&b[cb + 1]);
        o.z = sc * s.z + __ldg(&b[cb + 2]);
        o.w = sc * s.w + __ldg(&b[cb + 3]);
    } else {
        float sc = g_dinv2[node];
        o.x = sc * s.x; o.y = sc * s.y; o.z = sc * s.z; o.w = sc * s.w;
    }
    uout[(size_t)node * 16 + lane] = o;
}

// ---------------------------------------------------------------------------
extern "C" void kernel_launch(void* const* d_in, const int* in_sizes, int n_in,
                              void* d_out, int out_size) {
    const float* x  = (const float*)d_in[0];   // [100000,128]
    const void*  ei = d_in[1];                 // [2, E] int32 or int64
    const float* W  = (const float*)d_in[2];   // [64,128]
    const float* b  = (const float*)d_in[3];   // [64]
    float* out = (float*)d_out;

    const int E = in_sizes[1] / 2;             // 1,600,000

    const int T = 256;
    const int nb = (N_NODES + T - 1) / T;
    const int eb = (E + T - 1) / T;

    k_detect<<<1, 256>>>((const int*)ei);

    // CSR build (counting sort by target)
    k_zero<<<nb, T>>>();
    k_hist<<<eb, T>>>(ei, E);
    k_scan1<<<SCAN_B, SCAN_T>>>();
    k_scan2<<<1, 128>>>();
    k_scan3<<<SCAN_B, SCAN_T>>>();
    k_scatter<<<eb, T>>>(ei, E);

    // Input transform (linear layer folded in front; needs g_dinv from scan)
    k_gemm<<<2048, T>>>(x, W);

    // 3 gather hops (16 nodes per 256-thread block)
    const int hb = (N_NODES + 15) / 16;
    k_hop<0><<<hb, T>>>(nullptr, b);
    k_hop<1><<<hb, T>>>(nullptr, b);
    k_hop<2><<<hb, T>>>(out, b);
}

// round 7
// speedup vs baseline: 1.0191x; 1.0191x over previous
#include <cuda_runtime.h>
#include <cstdint>

#define N_NODES 100000
#define FEAT    64
#define NF      (N_NODES * FEAT)
#define E_MAX   1700000
#define SCAN_T  1024
#define SCAN_B  ((N_NODES + SCAN_T - 1) / SCAN_T)   // 98

// Scratch: device globals (no allocations allowed).
__device__ __align__(16) float g_u[NF];
__device__ __align__(16) float g_u2[NF];
__device__ int   g_cnt[N_NODES];
__device__ int   g_off[N_NODES + 1];
__device__ int   g_cur[N_NODES];
__device__ int   g_adj[E_MAX];
__device__ int   g_blk[SCAN_B];
__device__ float g_dinv[N_NODES];    // (deg)^{-1/2}, deg includes self-loop
__device__ float g_dinv2[N_NODES];   // (deg)^{-1}
__device__ int   g_is64;             // 1 if edge_index is int64, 0 if int32

// ---------------------------------------------------------------------------
// Deterministic dtype sniff: int64 node ids < 1e5 have zero high words.
__global__ void k_detect(const int* __restrict__ ei32) {
    __shared__ int any;
    if (threadIdx.x == 0) any = 0;
    __syncthreads();
    for (int i = threadIdx.x; i < 1024; i += blockDim.x)
        if (ei32[2 * i + 1] != 0) any = 1;     // benign race, same result
    __syncthreads();
    if (threadIdx.x == 0) g_is64 = (any == 0) ? 1 : 0;
}

__device__ __forceinline__ int edge_idx(const void* ei, int E, int half, int e) {
    if (g_is64) {
        long long v = ((const long long*)ei)[(size_t)half * E + e];
        return (int)v;
    }
    return ((const int*)ei)[(size_t)half * E + e];
}

// ---------------------------------------------------------------------------
__global__ void k_zero() {
    int i = blockIdx.x * blockDim.x + threadIdx.x;
    if (i < N_NODES) g_cnt[i] = 0;
}

__global__ void k_hist(const void* __restrict__ ei, int E) {
    int e = blockIdx.x * blockDim.x + threadIdx.x;
    if (e >= E) return;
    unsigned t = (unsigned)edge_idx(ei, E, 1, e);   // target i
    if (t < N_NODES) atomicAdd(&g_cnt[t], 1);
}

// --- grid-wide exclusive scan of g_cnt, 3 phases --------------------------
__global__ void k_scan1() {
    __shared__ int bs[SCAN_T];
    int i = blockIdx.x * SCAN_T + threadIdx.x;
    int v = (i < N_NODES) ? g_cnt[i] : 0;
    bs[threadIdx.x] = v;
    __syncthreads();
    for (int off = SCAN_T / 2; off > 0; off >>= 1) {
        if (threadIdx.x < off) bs[threadIdx.x] += bs[threadIdx.x + off];
        __syncthreads();
    }
    if (threadIdx.x == 0) g_blk[blockIdx.x] = bs[0];
}

__global__ void k_scan2() {
    __shared__ int bs[128];
    int t = threadIdx.x;
    int v = (t < SCAN_B) ? g_blk[t] : 0;
    bs[t] = v;
    __syncthreads();
    for (int off = 1; off < 128; off <<= 1) {       // Hillis-Steele inclusive
        int p = (t >= off) ? bs[t - off] : 0;
        __syncthreads();
        bs[t] += p;
        __syncthreads();
    }
    if (t < SCAN_B) g_blk[t] = bs[t] - v;           // exclusive
    if (t == 0) g_off[N_NODES] = bs[127];           // total
}

__global__ void k_scan3() {
    __shared__ int bs[SCAN_T];
    int t = threadIdx.x;
    int i = blockIdx.x * SCAN_T + t;
    int c = (i < N_NODES) ? g_cnt[i] : 0;
    bs[t] = c;
    __syncthreads();
    for (int off = 1; off < SCAN_T; off <<= 1) {    // Hillis-Steele inclusive
        int p = (t >= off) ? bs[t - off] : 0;
        __syncthreads();
        bs[t] += p;
        __syncthreads();
    }
    if (i < N_NODES) {
        int excl = g_blk[blockIdx.x] + bs[t] - c;
        g_off[i] = excl;
        g_cur[i] = excl;
        float deg = (float)c + 1.0f;        // self-loop
        g_dinv[i]  = rsqrtf(deg);
        g_dinv2[i] = 1.0f / deg;
    }
}

__global__ void k_scatter(const void* __restrict__ ei, int E) {
    int e = blockIdx.x * blockDim.x + threadIdx.x;
    if (e >= E) return;
    unsigned tgt = (unsigned)edge_idx(ei, E, 1, e);
    unsigned src = (unsigned)edge_idx(ei, E, 0, e);
    if (tgt >= N_NODES || src >= N_NODES) return;
    int pos = atomicAdd(&g_cur[tgt], 1);
    if (pos < E_MAX) g_adj[pos] = (int)src;
}

// ---------------------------------------------------------------------------
// u0[i,:] = dinv[i] * (x[i,:] @ W^T)   -- x:[N,128], W:[64,128]
__global__ void k_gemm(const float* __restrict__ x, const float* __restrict__ W) {
    __shared__ float Ws[128 * 64];   // Ws[k*64 + c] = W[c*128 + k]
    __shared__ float xs[4][128];

    int tid = threadIdx.x;
    for (int i = tid; i < 2048; i += 256) {
        float4 w4 = __ldg(&reinterpret_cast<const float4*>(W)[i]);
        int c = i >> 5;
        int k = (i & 31) << 2;
        Ws[(k + 0) * 64 + c] = w4.x;
        Ws[(k + 1) * 64 + c] = w4.y;
        Ws[(k + 2) * 64 + c] = w4.z;
        Ws[(k + 3) * 64 + c] = w4.w;
    }
    __syncthreads();

    int c = tid & 63;
    int r = tid >> 6;

    for (int rb = blockIdx.x * 4; rb < N_NODES; rb += gridDim.x * 4) {
        if (tid < 128) {
            int rr = tid >> 5;
            int k4 = (tid & 31);
            int rowi = rb + rr;
            float4 v = (rowi < N_NODES)
                ? __ldg(&reinterpret_cast<const float4*>(x)[(size_t)rowi * 32 + k4])
                : make_float4(0.f, 0.f, 0.f, 0.f);
            int k = k4 << 2;
            xs[rr][k + 0] = v.x;
            xs[rr][k + 1] = v.y;
            xs[rr][k + 2] = v.z;
            xs[rr][k + 3] = v.w;
        }
        __syncthreads();

        int rowi = rb + r;
        if (rowi < N_NODES) {
            float s = 0.0f;
            #pragma unroll
            for (int k = 0; k < 128; k++)
                s = fmaf(xs[r][k], Ws[k * 64 + c], s);
            g_u[(size_t)rowi * 64 + c] = g_dinv[rowi] * s;
        }
        __syncthreads();
    }
}

// ---------------------------------------------------------------------------
// Gather hop: halfwarp (16 threads) per node, one float4 column-group each.
// Unroll-4 with two accumulators: 4 independent gathers in flight per
// halfwarp, adj index loads are uniform-address (broadcast, L1-resident).
// PASS 0: g_u  -> g_u2, scale dinv2
// PASS 1: g_u2 -> g_u,  scale dinv2
// PASS 2: g_u  -> out,  scale dinv, + bias
template <int PASS>
__global__ void k_hop(float* __restrict__ outp, const float* __restrict__ b) {
    const float4* uin  = reinterpret_cast<const float4*>(PASS == 1 ? g_u2 : g_u);
    float4* uout = (PASS == 0) ? reinterpret_cast<float4*>(g_u2)
                 : (PASS == 1) ? reinterpret_cast<float4*>(g_u)
                               : reinterpret_cast<float4*>(outp);

    int tid  = threadIdx.x;
    int node = blockIdx.x * 16 + (tid >> 4);
    if (node >= N_NODES) return;
    int lane = tid & 15;

    int d   = g_off[node];
    int end = g_off[node + 1];

    float4 s0 = uin[(size_t)node * 16 + lane];     // self-loop term
    float4 s1 = make_float4(0.f, 0.f, 0.f, 0.f);

    for (; d + 3 < end; d += 4) {
        int j0 = __ldg(&g_adj[d + 0]);
        int j1 = __ldg(&g_adj[d + 1]);
        int j2 = __ldg(&g_adj[d + 2]);
        int j3 = __ldg(&g_adj[d + 3]);
        float4 a0 = __ldg(&uin[(size_t)j0 * 16 + lane]);
        float4 a1 = __ldg(&uin[(size_t)j1 * 16 + lane]);
        float4 a2 = __ldg(&uin[(size_t)j2 * 16 + lane]);
        float4 a3 = __ldg(&uin[(size_t)j3 * 16 + lane]);
        s0.x += a0.x + a1.x;  s0.y += a0.y + a1.y;
        s0.z += a0.z + a1.z;  s0.w += a0.w + a1.w;
        s1.x += a2.x + a3.x;  s1.y += a2.y + a3.y;
        s1.z += a2.z + a3.z;  s1.w += a2.w + a3.w;
    }
    for (; d < end; d++) {
        int j0 = __ldg(&g_adj[d]);
        float4 a0 = __ldg(&uin[(size_t)j0 * 16 + lane]);
        s0.x += a0.x; s0.y += a0.y; s0.z += a0.z; s0.w += a0.w;
    }
    s0.x += s1.x; s0.y += s1.y; s0.z += s1.z; s0.w += s1.w;

    float4 o;
    if (PASS == 2) {
        float sc = g_dinv[node];
        int cb = lane << 2;
        o.x = sc * s0.x + __ldg(&b[cb + 0]);
        o.y = sc * s0.y + __ldg(&b[cb + 1]);
        o.z = sc * s0.z + __ldg(&b[cb + 2]);
        o.w = sc * s0.w + __ldg(&b[cb + 3]);
    } else {
        float sc = g_dinv2[node];
        o.x = sc * s0.x; o.y = sc * s0.y; o.z = sc * s0.z; o.w = sc * s0.w;
    }
    uout[(size_t)node * 16 + lane] = o;
}

// ---------------------------------------------------------------------------
extern "C" void kernel_launch(void* const* d_in, const int* in_sizes, int n_in,
                              void* d_out, int out_size) {
    const float* x  = (const float*)d_in[0];   // [100000,128]
    const void*  ei = d_in[1];                 // [2, E] int32 or int64
    const float* W  = (const float*)d_in[2];   // [64,128]
    const float* b  = (const float*)d_in[3];   // [64]
    float* out = (float*)d_out;

    const int E = in_sizes[1] / 2;             // 1,600,000

    const int T = 256;
    const int nb = (N_NODES + T - 1) / T;
    const int eb = (E + T - 1) / T;

    k_detect<<<1, 256>>>((const int*)ei);

    // CSR build (counting sort by target)
    k_zero<<<nb, T>>>();
    k_hist<<<eb, T>>>(ei, E);
    k_scan1<<<SCAN_B, SCAN_T>>>();
    k_scan2<<<1, 128>>>();
    k_scan3<<<SCAN_B, SCAN_T>>>();
    k_scatter<<<eb, T>>>(ei, E);

    // Input transform (linear layer folded in front; needs g_dinv from scan)
    k_gemm<<<2048, T>>>(x, W);

    // 3 gather hops (16 nodes per 256-thread block)
    const int hb = (N_NODES + 15) / 16;
    k_hop<0><<<hb, T>>>(nullptr, b);
    k_hop<1><<<hb, T>>>(nullptr, b);
    k_hop<2><<<hb, T>>>(out, b);
}

// round 8
// speedup vs baseline: 1.0922x; 1.0717x over previous
#include <cuda_runtime.h>
#include <cstdint>

#define N_NODES 100000
#define FEAT    64
#define NF      (N_NODES * FEAT)
#define E_MAX   1700000
#define GRID    296            // 2 blocks/SM on 148 SMs (GB300 has 152)
#define TPB     512
#define CHUNK   338            // ceil(N_NODES / GRID); 296*338 = 100048
#define NBAR    8

// Scratch: device globals (no allocations allowed). Zero-initialized.
__device__ __align__(16) float g_u[NF];
__device__ __align__(16) float g_u2[NF];
__device__ int   g_cnt[N_NODES];
__device__ int   g_off[N_NODES + 1];
__device__ int   g_cur[N_NODES];
__device__ int   g_adj[E_MAX];
__device__ int   g_blk[GRID];
__device__ float g_dinv[N_NODES];    // (deg)^{-1/2}, deg includes self-loop
__device__ float g_dinv2[N_NODES];   // (deg)^{-1}
__device__ int   g_is64;             // 1 if edge_index is int64, 0 if int32
// Grid barrier state. Slot k's flag is reset at release of slot k+1 (circular),
// so all state returns to a reusable configuration every launch (replay-safe).
__device__ unsigned      g_bar_cnt[NBAR];
__device__ volatile int  g_bar_flag[NBAR];

// ---------------------------------------------------------------------------
__device__ __forceinline__ void grid_barrier(int slot) {
    __syncthreads();
    if (threadIdx.x == 0) {
        __threadfence();
        unsigned old = atomicAdd(&g_bar_cnt[slot], 1u);
        if (old == GRID - 1) {
            g_bar_cnt[slot] = 0;                          // self-clean counter
            g_bar_flag[(slot + NBAR - 1) % NBAR] = 0;     // reset previous slot
            __threadfence();
            g_bar_flag[slot] = 1;                         // release
        } else {
            while (g_bar_flag[slot] == 0) { __nanosleep(64); }
            __threadfence();
        }
    }
    __syncthreads();
}

__device__ __forceinline__ int edge_idx(const void* ei, int E, int half, int e) {
    if (g_is64) return (int)((const long long*)ei)[(size_t)half * E + e];
    return ((const int*)ei)[(size_t)half * E + e];
}

// ---------------------------------------------------------------------------
// Gather hop: halfwarp (16 threads) per node, one float4 column-group each.
// PASS 0: g_u -> g_u2 (dinv2); PASS 1: g_u2 -> g_u (dinv2);
// PASS 2: g_u -> out (dinv, +bias).
template <int PASS>
__device__ void hop_phase(float* __restrict__ outp, const float* __restrict__ b) {
    const float4* uin = reinterpret_cast<const float4*>(PASS == 1 ? g_u2 : g_u);
    float4* uout = (PASS == 0) ? reinterpret_cast<float4*>(g_u2)
                 : (PASS == 1) ? reinterpret_cast<float4*>(g_u)
                               : reinterpret_cast<float4*>(outp);
    int lane = threadIdx.x & 15;
    int hw   = threadIdx.x >> 4;        // 0..31 halfwarps per block

    for (int base = blockIdx.x * 32; base < N_NODES; base += GRID * 32) {
        int node = base + hw;
        if (node >= N_NODES) continue;

        int d   = g_off[node];
        int end = g_off[node + 1];

        float4 s0 = uin[(size_t)node * 16 + lane];   // self-loop term
        float4 s1 = make_float4(0.f, 0.f, 0.f, 0.f);

        for (; d + 3 < end; d += 4) {
            int j0 = __ldg(&g_adj[d + 0]);
            int j1 = __ldg(&g_adj[d + 1]);
            int j2 = __ldg(&g_adj[d + 2]);
            int j3 = __ldg(&g_adj[d + 3]);
            float4 a0 = __ldg(&uin[(size_t)j0 * 16 + lane]);
            float4 a1 = __ldg(&uin[(size_t)j1 * 16 + lane]);
            float4 a2 = __ldg(&uin[(size_t)j2 * 16 + lane]);
            float4 a3 = __ldg(&uin[(size_t)j3 * 16 + lane]);
            s0.x += a0.x + a1.x;  s0.y += a0.y + a1.y;
            s0.z += a0.z + a1.z;  s0.w += a0.w + a1.w;
            s1.x += a2.x + a3.x;  s1.y += a2.y + a3.y;
            s1.z += a2.z + a3.z;  s1.w += a2.w + a3.w;
        }
        for (; d < end; d++) {
            int j0 = __ldg(&g_adj[d]);
            float4 a0 = __ldg(&uin[(size_t)j0 * 16 + lane]);
            s0.x += a0.x; s0.y += a0.y; s0.z += a0.z; s0.w += a0.w;
        }
        s0.x += s1.x; s0.y += s1.y; s0.z += s1.z; s0.w += s1.w;

        float4 o;
        if (PASS == 2) {
            float sc = g_dinv[node];
            int cb = lane << 2;
            o.x = sc * s0.x + __ldg(&b[cb + 0]);
            o.y = sc * s0.y + __ldg(&b[cb + 1]);
            o.z = sc * s0.z + __ldg(&b[cb + 2]);
            o.w = sc * s0.w + __ldg(&b[cb + 3]);
        } else {
            float sc = g_dinv2[node];
            o.x = sc * s0.x; o.y = sc * s0.y; o.z = sc * s0.z; o.w = sc * s0.w;
        }
        uout[(size_t)node * 16 + lane] = o;
    }
}

// ---------------------------------------------------------------------------
__global__ void __launch_bounds__(TPB, 2)
sgc_mono(const float* __restrict__ x, const void* __restrict__ ei, int E,
         const float* __restrict__ W, const float* __restrict__ b,
         float* __restrict__ out) {
    __shared__ __align__(16) char s_mem[37120];   // max phase: gemm 36864 B
    float* Ws = reinterpret_cast<float*>(s_mem);              // [128*64]
    float* xs = reinterpret_cast<float*>(s_mem + 32768);      // [8*128]
    int*   bs = reinterpret_cast<int*>(s_mem);                // scan scratch

    const int tid = threadIdx.x;
    const int bid = blockIdx.x;
    const int gthread = bid * TPB + tid;
    const int gstride = GRID * TPB;

    // ---- Phase 0: zero histogram + dtype detect ---------------------------
    for (int i = gthread; i < N_NODES; i += gstride) g_cnt[i] = 0;
    if (bid == 0) {
        __shared__ int any;
        if (tid == 0) any = 0;
        __syncthreads();
        const int* ei32 = (const int*)ei;
        for (int i = tid; i < 1024; i += TPB)
            if (ei32[2 * i + 1] != 0) any = 1;   // benign race
        __syncthreads();
        if (tid == 0) g_is64 = (any == 0) ? 1 : 0;
    }
    grid_barrier(0);

    // ---- Phase 1: degree histogram ----------------------------------------
    for (int e = gthread; e < E; e += gstride) {
        unsigned t = (unsigned)edge_idx(ei, E, 1, e);
        if (t < N_NODES) atomicAdd(&g_cnt[t], 1);
    }
    grid_barrier(1);

    // ---- Phase 2: per-block chunk sums ------------------------------------
    {
        int beg = bid * CHUNK;
        int len = N_NODES - beg; if (len > CHUNK) len = CHUNK; if (len < 0) len = 0;
        int v = (tid < len) ? g_cnt[beg + tid] : 0;
        bs[tid] = v;
        __syncthreads();
        for (int off = TPB / 2; off > 0; off >>= 1) {
            if (tid < off) bs[tid] += bs[tid + off];
            __syncthreads();
        }
        if (tid == 0) g_blk[bid] = bs[0];
    }
    grid_barrier(2);

    // ---- Phase 3: block 0 scans the 296 block sums ------------------------
    if (bid == 0) {
        int v = (tid < GRID) ? g_blk[tid] : 0;
        bs[tid] = v;
        __syncthreads();
        for (int off = 1; off < TPB; off <<= 1) {    // Hillis-Steele inclusive
            int p = (tid >= off) ? bs[tid - off] : 0;
            __syncthreads();
            bs[tid] += p;
            __syncthreads();
        }
        if (tid < GRID) g_blk[tid] = bs[tid] - v;    // exclusive
        if (tid == 0) g_off[N_NODES] = bs[TPB - 1];
    }
    grid_barrier(3);

    // ---- Phase 4: per-chunk exclusive scan + dinv/dinv2 --------------------
    {
        int beg = bid * CHUNK;
        int len = N_NODES - beg; if (len > CHUNK) len = CHUNK; if (len < 0) len = 0;
        int c = (tid < len) ? g_cnt[beg + tid] : 0;
        bs[tid] = c;
        __syncthreads();
        for (int off = 1; off < TPB; off <<= 1) {
            int p = (tid >= off) ? bs[tid - off] : 0;
            __syncthreads();
            bs[tid] += p;
            __syncthreads();
        }
        if (tid < len) {
            int excl = g_blk[bid] + bs[tid] - c;
            int i = beg + tid;
            g_off[i] = excl;
            g_cur[i] = excl;
            float deg = (float)c + 1.0f;
            g_dinv[i]  = rsqrtf(deg);
            g_dinv2[i] = 1.0f / deg;
        }
    }
    grid_barrier(4);

    // ---- Phase 5: scatter (CSR fill) then GEMM (independent, no barrier) --
    for (int e = gthread; e < E; e += gstride) {
        unsigned t = (unsigned)edge_idx(ei, E, 1, e);
        unsigned s = (unsigned)edge_idx(ei, E, 0, e);
        if (t >= N_NODES || s >= N_NODES) continue;
        int pos = atomicAdd(&g_cur[t], 1);
        if (pos < E_MAX) g_adj[pos] = (int)s;
    }
    // GEMM: u0[i,:] = dinv[i] * (x[i,:] @ W^T)
    {
        __syncthreads();   // bs scratch -> Ws reuse
        for (int i = tid; i < 2048; i += TPB) {
            float4 w4 = __ldg(&reinterpret_cast<const float4*>(W)[i]);
            int c = i >> 5;
            int k = (i & 31) << 2;
            Ws[(k + 0) * 64 + c] = w4.x;
            Ws[(k + 1) * 64 + c] = w4.y;
            Ws[(k + 2) * 64 + c] = w4.z;
            Ws[(k + 3) * 64 + c] = w4.w;
        }
        __syncthreads();
        int c = tid & 63;
        int r = tid >> 6;   // 0..7
        for (int rb = bid * 8; rb < N_NODES; rb += GRID * 8) {
            if (tid < 256) {
                int rr = tid >> 5;          // row 0..7
                int k4 = tid & 31;
                int rowi = rb + rr;
                float4 v = (rowi < N_NODES)
                    ? __ldg(&reinterpret_cast<const float4*>(x)[(size_t)rowi * 32 + k4])
                    : make_float4(0.f, 0.f, 0.f, 0.f);
                int k = k4 << 2;
                xs[rr * 128 + k + 0] = v.x;
                xs[rr * 128 + k + 1] = v.y;
                xs[rr * 128 + k + 2] = v.z;
                xs[rr * 128 + k + 3] = v.w;
            }
            __syncthreads();
            int rowi = rb + r;
            if (rowi < N_NODES) {
                float s = 0.0f;
                #pragma unroll
                for (int k = 0; k < 128; k++)
                    s = fmaf(xs[r * 128 + k], Ws[k * 64 + c], s);
                g_u[(size_t)rowi * 64 + c] = g_dinv[rowi] * s;
            }
            __syncthreads();
        }
    }
    grid_barrier(5);

    // ---- Phases 6-8: three gather hops -------------------------------------
    hop_phase<0>(nullptr, b);
    grid_barrier(6);
    hop_phase<1>(nullptr, b);
    grid_barrier(7);
    hop_phase<2>(out, b);
}

// ---------------------------------------------------------------------------
extern "C" void kernel_launch(void* const* d_in, const int* in_sizes, int n_in,
                              void* d_out, int out_size) {
    const float* x  = (const float*)d_in[0];   // [100000,128]
    const void*  ei = d_in[1];                 // [2, E] int32 or int64
    const float* W  = (const float*)d_in[2];   // [64,128]
    const float* b  = (const float*)d_in[3];   // [64]
    float* out = (float*)d_out;

    const int E = in_sizes[1] / 2;             // 1,600,000

    sgc_mono<<<GRID, TPB>>>(x, ei, E, W, b, out);
}